// round 1
// baseline (speedup 1.0000x reference)
#include <cuda_runtime.h>
#include <math.h>

// Problem constants (fixed by the dataset: features [512,384] f32, labels [512] i32)
#define NQ 512
#define DIM 384
#define HALF_INV_T2 50.0f   // 1/(2*t2), t2 = 0.01
#define KSEL 6.0f           // K = 5 + 1

// Scratch (no allocations allowed in kernel_launch)
__device__ float g_sq[NQ];          // row squared norms
__device__ float g_gram[NQ * NQ];   // F @ F^T
__device__ float g_prec[NQ];        // per-query unnormalized precision sum

__device__ __forceinline__ float fast_tanh(float x) {
    float r;
    asm("tanh.approx.f32 %0, %1;" : "=f"(r) : "f"(x));
    return r;
}

// ---------------------------------------------------------------------------
// Kernel 1: squared norms, one block per row
// ---------------------------------------------------------------------------
__global__ __launch_bounds__(128) void sq_kernel(const float* __restrict__ F) {
    const int q = blockIdx.x;
    const int t = threadIdx.x;
    float s = 0.0f;
    #pragma unroll
    for (int i = t; i < DIM; i += 128) {
        float v = F[q * DIM + i];
        s = fmaf(v, v, s);
    }
    #pragma unroll
    for (int o = 16; o; o >>= 1) s += __shfl_xor_sync(0xffffffffu, s, o);
    __shared__ float ws[4];
    if ((t & 31) == 0) ws[t >> 5] = s;
    __syncthreads();
    if (t == 0) g_sq[q] = ws[0] + ws[1] + ws[2] + ws[3];
}

// ---------------------------------------------------------------------------
// Kernel 2: Gram matrix G = F F^T, tiled 32(M) x 64(N), K-chunks of 32.
// 256 threads, each computes a 2x4 micro-tile. FMA-pipe bound.
// ---------------------------------------------------------------------------
__global__ __launch_bounds__(256) void gram_kernel(const float* __restrict__ F) {
    __shared__ float As[32][33];   // [row][k]
    __shared__ float Bs[32][68];   // [k][col], pad 68 for alignment + fewer conflicts

    const int bm = blockIdx.y * 32;
    const int bn = blockIdx.x * 64;
    const int t  = threadIdx.x;
    const int r0 = (t >> 4) * 2;   // 0,2,...,30
    const int c0 = (t & 15) * 4;   // 0,4,...,60

    float acc[2][4] = {};

    for (int k0 = 0; k0 < DIM; k0 += 32) {
        // A tile: 32x32, coalesced
        #pragma unroll
        for (int i = t; i < 32 * 32; i += 256) {
            int r = i >> 5, c = i & 31;
            As[r][c] = F[(bm + r) * DIM + k0 + c];
        }
        // B tile: 64 rows x 32 k, stored transposed as Bs[k][col]
        #pragma unroll
        for (int i = t; i < 64 * 32; i += 256) {
            int c = i >> 5, kk = i & 31;
            Bs[kk][c] = F[(bn + c) * DIM + k0 + kk];
        }
        __syncthreads();

        #pragma unroll
        for (int kk = 0; kk < 32; kk++) {
            float a0 = As[r0][kk];
            float a1 = As[r0 + 1][kk];
            float4 b = *reinterpret_cast<const float4*>(&Bs[kk][c0]);
            acc[0][0] = fmaf(a0, b.x, acc[0][0]);
            acc[0][1] = fmaf(a0, b.y, acc[0][1]);
            acc[0][2] = fmaf(a0, b.z, acc[0][2]);
            acc[0][3] = fmaf(a0, b.w, acc[0][3]);
            acc[1][0] = fmaf(a1, b.x, acc[1][0]);
            acc[1][1] = fmaf(a1, b.y, acc[1][1]);
            acc[1][2] = fmaf(a1, b.z, acc[1][2]);
            acc[1][3] = fmaf(a1, b.w, acc[1][3]);
        }
        __syncthreads();
    }

    #pragma unroll
    for (int i = 0; i < 2; i++) {
        #pragma unroll
        for (int j = 0; j < 4; j++) {
            g_gram[(bm + r0 + i) * NQ + (bn + c0 + j)] = acc[i][j];
        }
    }
}

// ---------------------------------------------------------------------------
// Kernel 3: rank + precision. One block per query q, one thread per gallery g.
//   a[g] = d(q,g) * 50;  rank = 256 + 0.5 * sum_j tanh(a_g - a_j)
//   contrib = (lbl[q]==lbl[g]) ? sigmoid(6 - rank) : 0;  block-reduce -> g_prec
// ---------------------------------------------------------------------------
__global__ __launch_bounds__(NQ) void rank_kernel(const int* __restrict__ labels) {
    __shared__ float a[NQ];
    __shared__ float ws[16];

    const int q = blockIdx.x;
    const int g = threadIdx.x;

    float d2 = g_sq[q] + g_sq[g] - 2.0f * g_gram[q * NQ + g];
    float d  = sqrtf(fmaxf(d2, 0.0f));
    a[g] = d * HALF_INV_T2;
    __syncthreads();

    const float ag = a[g];
    float acc = 0.0f;
    #pragma unroll 8
    for (int j = 0; j < NQ; j++) {
        acc += fast_tanh(ag - a[j]);
    }
    float rank = 0.5f * (float)NQ + 0.5f * acc;

    float contrib = 0.0f;
    if (labels[q] == labels[g]) {
        // sigmoid((K - rank)/t1), t1 = 1
        contrib = 1.0f / (1.0f + __expf(rank - KSEL));
    }

    #pragma unroll
    for (int o = 16; o; o >>= 1) contrib += __shfl_xor_sync(0xffffffffu, contrib, o);
    if ((g & 31) == 0) ws[g >> 5] = contrib;
    __syncthreads();
    if (g < 16) {
        float s = ws[g];
        #pragma unroll
        for (int o = 8; o; o >>= 1) s += __shfl_xor_sync(0x0000ffffu, s, o);
        if (g == 0) g_prec[q] = s;
    }
}

// ---------------------------------------------------------------------------
// Kernel 4: deterministic final reduction -> scalar loss
// ---------------------------------------------------------------------------
__global__ __launch_bounds__(NQ) void final_kernel(float* __restrict__ out) {
    __shared__ float ws[16];
    const int t = threadIdx.x;
    float v = g_prec[t];
    #pragma unroll
    for (int o = 16; o; o >>= 1) v += __shfl_xor_sync(0xffffffffu, v, o);
    if ((t & 31) == 0) ws[t >> 5] = v;
    __syncthreads();
    if (t < 16) {
        float s = ws[t];
        #pragma unroll
        for (int o = 8; o; o >>= 1) s += __shfl_xor_sync(0x0000ffffu, s, o);
        if (t == 0) out[0] = 1.0f - s / (KSEL * (float)NQ);
    }
}

// ---------------------------------------------------------------------------
extern "C" void kernel_launch(void* const* d_in, const int* in_sizes, int n_in,
                              void* d_out, int out_size) {
    const float* F      = (const float*)d_in[0];
    const int*   labels = (const int*)d_in[1];
    float*       out    = (float*)d_out;

    sq_kernel<<<NQ, 128>>>(F);
    gram_kernel<<<dim3(NQ / 64, NQ / 32), 256>>>(F);
    rank_kernel<<<NQ, NQ>>>(labels);
    final_kernel<<<1, NQ>>>(out);
}

// round 2
// speedup vs baseline: 1.3821x; 1.3821x over previous
#include <cuda_runtime.h>
#include <math.h>

// Problem constants (fixed: features [512,384] f32, labels [512] i32)
#define NQ 512
#define DIM 384
#define SCALE 50.0f          // 1/(2*t2), t2 = 0.01  (tanh form of sigmoid)
#define KSEL 6.0f            // K = 5 + 1
#define SAT 9.0f             // |x| >= 9 -> tanh(x) == +/-1 exactly in fp32

// Scratch (no allocations allowed anywhere)
__device__ float g_gram[NQ * NQ];   // F @ F^T
__device__ float g_prec[NQ];        // per-query unnormalized precision sum

__device__ __forceinline__ float fast_tanh(float x) {
    float r;
    asm("tanh.approx.f32 %0, %1;" : "=f"(r) : "f"(x));
    return r;
}

// ---------------------------------------------------------------------------
// Kernel 1: Gram matrix G = F F^T, tiled 32(M) x 64(N), K-chunks of 32.
// 256 threads, 2x4 micro-tile per thread. FFMA-pipe bound (~5-6us).
// ---------------------------------------------------------------------------
__global__ __launch_bounds__(256) void gram_kernel(const float* __restrict__ F) {
    __shared__ float As[32][33];   // [row][k]
    __shared__ float Bs[32][68];   // [k][col]

    const int bm = blockIdx.y * 32;
    const int bn = blockIdx.x * 64;
    const int t  = threadIdx.x;
    const int r0 = (t >> 4) * 2;
    const int c0 = (t & 15) * 4;

    float acc[2][4] = {};

    for (int k0 = 0; k0 < DIM; k0 += 32) {
        #pragma unroll
        for (int i = t; i < 32 * 32; i += 256) {
            int r = i >> 5, c = i & 31;
            As[r][c] = F[(bm + r) * DIM + k0 + c];
        }
        #pragma unroll
        for (int i = t; i < 64 * 32; i += 256) {
            int c = i >> 5, kk = i & 31;
            Bs[kk][c] = F[(bn + c) * DIM + k0 + kk];
        }
        __syncthreads();

        #pragma unroll
        for (int kk = 0; kk < 32; kk++) {
            float a0 = As[r0][kk];
            float a1 = As[r0 + 1][kk];
            float4 b = *reinterpret_cast<const float4*>(&Bs[kk][c0]);
            acc[0][0] = fmaf(a0, b.x, acc[0][0]);
            acc[0][1] = fmaf(a0, b.y, acc[0][1]);
            acc[0][2] = fmaf(a0, b.z, acc[0][2]);
            acc[0][3] = fmaf(a0, b.w, acc[0][3]);
            acc[1][0] = fmaf(a1, b.x, acc[1][0]);
            acc[1][1] = fmaf(a1, b.y, acc[1][1]);
            acc[1][2] = fmaf(a1, b.z, acc[1][2]);
            acc[1][3] = fmaf(a1, b.w, acc[1][3]);
        }
        __syncthreads();
    }

    #pragma unroll
    for (int i = 0; i < 2; i++) {
        #pragma unroll
        for (int j = 0; j < 4; j++) {
            g_gram[(bm + r0 + i) * NQ + (bn + c0 + j)] = acc[i][j];
        }
    }
}

// ---------------------------------------------------------------------------
// Kernel 2: rank + precision via per-query sort + saturation pruning.
// One block of 512 threads per query q.
//   a[g] = 50 * d(q,g); sort; rank from sorted position + tanh corrections
//   over the |delta| < 9 window only (tanh saturates exactly in fp32 beyond).
// ---------------------------------------------------------------------------
__global__ __launch_bounds__(NQ) void rank_kernel(const int* __restrict__ labels) {
    __shared__ float sv[NQ];   // sorted values
    __shared__ int   si[NQ];   // original gallery index per sorted slot
    __shared__ float ws[16];

    const int q = blockIdx.x;
    const int p = threadIdx.x;

    // distances from Gram matrix (diagonal = squared norms)
    {
        float Gqg = g_gram[q * NQ + p];
        float sqq = g_gram[q * (NQ + 1)];        // broadcast
        float sqg = g_gram[p * (NQ + 1)];
        float d2  = sqq + sqg - 2.0f * Gqg;
        sv[p] = SCALE * sqrtf(fmaxf(d2, 0.0f));
        si[p] = p;
    }
    __syncthreads();

    // Bitonic sort (ascending) of (sv, si) pairs. Deterministic incl. ties.
    for (int k = 2; k <= NQ; k <<= 1) {
        for (int j = k >> 1; j > 0; j >>= 1) {
            const int ixj = p ^ j;
            float myv = sv[p];
            int   myi = si[p];
            float ov  = sv[ixj];
            int   oi  = si[ixj];
            __syncthreads();
            const bool lowSlot = (ixj > p);
            const bool asc     = ((p & k) == 0);
            const bool wantMin = (lowSlot == asc);
            const bool take    = wantMin ? (ov < myv) : (ov > myv);
            if (take) { myv = ov; myi = oi; }
            sv[p] = myv;
            si[p] = myi;
            __syncthreads();
        }
    }

    const float val = sv[p];

    // rank = 256 + 0.5 * [ p - (511-p) + corrections ]
    float corr = 0.0f;
    for (int j = p - 1; j >= 0; --j) {            // left: dv in (0, inf)
        float dv = val - sv[j];
        if (dv >= SAT) break;
        corr += fast_tanh(dv) - 1.0f;
    }
    for (int j = p + 1; j < NQ; ++j) {            // right: dv in (-inf, 0)
        float dv = val - sv[j];
        if (dv <= -SAT) break;
        corr += fast_tanh(dv) + 1.0f;
    }
    const float rank = 0.5f * (float)NQ
                     + 0.5f * ((float)(2 * p - (NQ - 1)) + corr);

    // masked precision contribution
    float contrib = 0.0f;
    if (labels[q] == labels[si[p]]) {
        contrib = 1.0f / (1.0f + __expf(rank - KSEL));   // sigmoid(K - rank)
    }

    // block reduction (deterministic: fixed sorted order, fixed tree)
    #pragma unroll
    for (int o = 16; o; o >>= 1) contrib += __shfl_xor_sync(0xffffffffu, contrib, o);
    if ((p & 31) == 0) ws[p >> 5] = contrib;
    __syncthreads();
    if (p < 16) {
        float s = ws[p];
        #pragma unroll
        for (int o = 8; o; o >>= 1) s += __shfl_xor_sync(0x0000ffffu, s, o);
        if (p == 0) g_prec[q] = s;
    }
}

// ---------------------------------------------------------------------------
// Kernel 3: deterministic final reduction -> scalar loss
// ---------------------------------------------------------------------------
__global__ __launch_bounds__(NQ) void final_kernel(float* __restrict__ out) {
    __shared__ float ws[16];
    const int t = threadIdx.x;
    float v = g_prec[t];
    #pragma unroll
    for (int o = 16; o; o >>= 1) v += __shfl_xor_sync(0xffffffffu, v, o);
    if ((t & 31) == 0) ws[t >> 5] = v;
    __syncthreads();
    if (t < 16) {
        float s = ws[t];
        #pragma unroll
        for (int o = 8; o; o >>= 1) s += __shfl_xor_sync(0x0000ffffu, s, o);
        if (t == 0) out[0] = 1.0f - s / (KSEL * (float)NQ);
    }
}

// ---------------------------------------------------------------------------
extern "C" void kernel_launch(void* const* d_in, const int* in_sizes, int n_in,
                              void* d_out, int out_size) {
    const float* F      = (const float*)d_in[0];
    const int*   labels = (const int*)d_in[1];
    float*       out    = (float*)d_out;

    gram_kernel<<<dim3(NQ / 64, NQ / 32), 256>>>(F);
    rank_kernel<<<NQ, NQ>>>(labels);
    final_kernel<<<1, NQ>>>(out);
}